// round 14
// baseline (speedup 1.0000x reference)
#include <cuda_runtime.h>
#include <math.h>

#define Bn 64
#define Nn 128
#define Dn 32
#define Gn 127              // N-1
#define Pn (Nn*(Nn-1))      // 16256
#define HFn 16
#define EPSf 1e-5f

typedef unsigned int u32;

// ---------------- scratch (static device globals; no allocation) -------------
__device__ float g_U[Bn*Nn*Dn];
__device__ float g_V[Bn*Nn*Dn];
__device__ float g_sumU[Nn], g_sumU2[Nn], g_sumV[Nn], g_sumV2[Nn];
__device__ float g_C[Nn*Nn];
__device__ float g_f[Bn*Nn*HFn];
__device__ float g_fsum[HFn], g_fsum2[HFn];

__device__ __forceinline__ float leaky(float x) { return x > 0.f ? x : 0.01f * x; }

__device__ __forceinline__ u32 tf32b(float x) {
    u32 y; asm("cvt.rna.tf32.f32 %0, %1;" : "=r"(y) : "f"(x));
    return y;
}
__device__ __forceinline__ void mma_tf32(float* d, const u32* a, const u32* b) {
    asm volatile(
        "mma.sync.aligned.m16n8k8.row.col.f32.tf32.tf32.f32 "
        "{%0,%1,%2,%3}, {%4,%5,%6,%7}, {%8,%9}, {%0,%1,%2,%3};"
        : "+f"(d[0]), "+f"(d[1]), "+f"(d[2]), "+f"(d[3])
        : "r"(a[0]), "r"(a[1]), "r"(a[2]), "r"(a[3]), "r"(b[0]), "r"(b[1]));
}

// ---------------- Kernel A: per-node projections + stats + zeroing -----------
// grid = 128, block = 256: thread = (b 0..63, cq 0..3), 8 channels each
__global__ void kA(const float* __restrict__ inp, const float* __restrict__ W1,
                   const float* __restrict__ b1) {
    const int n = blockIdx.x;
    const int tid = threadIdx.x;
    const int b = tid >> 2, cq = tid & 3;
    __shared__ __align__(16) float W1t[32*64];   // W1t[c*64 + k] = W1[k*32 + c]
    __shared__ float red[64*4];

    if (tid < 128) g_C[n*128 + tid] = 0.f;
    if (n == 0 && tid < HFn) { g_fsum[tid] = 0.f; g_fsum2[tid] = 0.f; }

    for (int idx = tid; idx < 2048; idx += 256) {
        int k = idx & 63, c = idx >> 6;
        W1t[c*64 + k] = W1[k*32 + c];
    }
    __syncthreads();

    float x[32];
    const float4* xp = (const float4*)(inp + ((size_t)b*Nn + n)*Dn);
    #pragma unroll
    for (int q = 0; q < 8; q++) {
        float4 v = xp[q];
        x[4*q+0]=v.x; x[4*q+1]=v.y; x[4*q+2]=v.z; x[4*q+3]=v.w;
    }
    float su=0.f, su2=0.f, sv=0.f, sv2=0.f;
    float ub[8], vb[8];
    #pragma unroll
    for (int cc = 0; cc < 8; cc++) {
        const int c = cq*8 + cc;
        const float4* wr = (const float4*)(W1t + c*64);
        float u = b1[c], v = 0.f;
        #pragma unroll
        for (int j = 0; j < 8; j++) {
            float4 wu = wr[j], wv = wr[8 + j];
            u += x[4*j+0]*wu.x + x[4*j+1]*wu.y + x[4*j+2]*wu.z + x[4*j+3]*wu.w;
            v += x[4*j+0]*wv.x + x[4*j+1]*wv.y + x[4*j+2]*wv.z + x[4*j+3]*wv.w;
        }
        ub[cc] = u; vb[cc] = v;
        su += u; su2 += u*u; sv += v; sv2 += v*v;
    }
    {
        float4* Uo = (float4*)(g_U + ((size_t)b*Nn + n)*Dn + cq*8);
        float4* Vo = (float4*)(g_V + ((size_t)b*Nn + n)*Dn + cq*8);
        Uo[0] = make_float4(ub[0], ub[1], ub[2], ub[3]);
        Uo[1] = make_float4(ub[4], ub[5], ub[6], ub[7]);
        Vo[0] = make_float4(vb[0], vb[1], vb[2], vb[3]);
        Vo[1] = make_float4(vb[4], vb[5], vb[6], vb[7]);
    }
    // reduce over cq (lane bits 0-1)
    #pragma unroll
    for (int s = 1; s <= 2; s <<= 1) {
        su  += __shfl_xor_sync(0xffffffffu, su,  s);
        su2 += __shfl_xor_sync(0xffffffffu, su2, s);
        sv  += __shfl_xor_sync(0xffffffffu, sv,  s);
        sv2 += __shfl_xor_sync(0xffffffffu, sv2, s);
    }
    if (cq == 0) { red[b] = su; red[64+b] = su2; red[128+b] = sv; red[192+b] = sv2; }
    __syncthreads();
    for (int s = 32; s > 0; s >>= 1) {
        if (tid < s) {
            red[tid] += red[tid+s]; red[64+tid] += red[64+tid+s];
            red[128+tid] += red[128+tid+s]; red[192+tid] += red[192+tid+s];
        }
        __syncthreads();
    }
    if (tid == 0) {
        g_sumU[n] = red[0]; g_sumU2[n] = red[64];
        g_sumV[n] = red[128]; g_sumV2[n] = red[192];
    }
}

// ---------------- Kernel B: cross term C[s,t], K-split x8 --------------------
__global__ void kB() {
    const int t0 = blockIdx.x * 16;
    const int s0 = blockIdx.y * 16;
    const int bz = blockIdx.z * 8;
    const int tx = threadIdx.x & 15;
    const int ty = threadIdx.x >> 4;
    __shared__ __align__(16) float Us[16][36];
    __shared__ __align__(16) float Vs[16][36];
    float acc = 0.f;
    for (int b = bz; b < bz + 8; b++) {
        __syncthreads();
        {
            int idx = threadIdx.x;
            int r = idx >> 5, c = idx & 31;
            Us[r][c] = g_U[((size_t)b*Nn + s0 + r)*Dn + c];
            Vs[r][c] = g_V[((size_t)b*Nn + t0 + r)*Dn + c];
            idx += 256; r = idx >> 5; c = idx & 31;
            Us[r][c] = g_U[((size_t)b*Nn + s0 + r)*Dn + c];
            Vs[r][c] = g_V[((size_t)b*Nn + t0 + r)*Dn + c];
        }
        __syncthreads();
        #pragma unroll
        for (int q = 0; q < 8; q++) {
            float4 u = *(const float4*)&Us[ty][4*q];
            float4 v = *(const float4*)&Vs[tx][4*q];
            acc += u.x*v.x + u.y*v.y + u.z*v.z + u.w*v.w;
        }
    }
    atomicAdd(&g_C[(s0+ty)*Nn + (t0+tx)], acc);
}

// ---------------- Kernel C: mma.sync tf32, fused agg->f epilogue -------------
// grid = (128, 16), block = 128 (4 warps); each CTA does 4 batch tiles.
__global__ void __launch_bounds__(128, 4) kC(
        const float* __restrict__ inp,
        const float* __restrict__ W2, const float* __restrict__ b2,
        const float* __restrict__ W3, const float* __restrict__ b3,
        const float* __restrict__ Wf1, const float* __restrict__ bf1,
        const float* __restrict__ g1, const float* __restrict__ be1,
        float* __restrict__ outEdges) {
    __shared__ __align__(16) float buf[128*36];   // V staging
    __shared__ float W3s[1056], w3c0[32], b2s[32], b3s[36];
    __shared__ float us[4][32], xs[4][32], scs[128], shs[128];
    __shared__ float zw[4][36];                   // per-warp col sums + G
    __shared__ float M1[16*32], v1[16], xdot[4][16];

    const int i   = blockIdx.x;
    const int bb  = blockIdx.y * 4;
    const int tid = threadIdx.x;
    const int warp = tid >> 5;
    const int lane = tid & 31;
    const int g = lane >> 2, c = lane & 3;
    const int wrow = warp * 32;

    // ---- one-time staging ----
    for (int idx = tid; idx < 1056; idx += 128) W3s[idx] = W3[idx];
    if (tid < 32) { w3c0[tid] = W3[tid*33]; b2s[tid] = b2[tid]; }
    if (tid < 33) b3s[tid] = b3[tid];
    {
        const int b = tid >> 5, k = tid & 31;
        us[b][k] = g_U[((size_t)(bb+b)*Nn + i)*Dn + k];
        xs[b][k] = inp[((size_t)(bb+b)*Nn + i)*Dn + k];
    }
    if (tid < 127) {
        const int t = tid + (tid >= i);
        const int p = i * Gn + tid;
        const float inv = 1.0f / 2048.0f;
        float m  = (g_sumU[i] + g_sumV[t]) * inv;
        float e2 = (g_sumU2[i] + g_sumV2[t] + 2.0f * g_C[i*Nn + t]) * inv;
        float sc = rsqrtf(e2 - m*m + EPSf) * g1[p];
        scs[tid] = sc; shs[tid] = be1[p] - m * sc;
    } else if (tid == 127) { scs[127] = 0.f; shs[127] = 0.f; }

    // ---- B fragments (W2, k x n), tf32, persistent ----
    u32 bf[4][4][2];
    #pragma unroll
    for (int kk = 0; kk < 4; kk++)
        #pragma unroll
        for (int nj = 0; nj < 4; nj++) {
            bf[kk][nj][0] = tf32b(W2[(kk*8 + c)*32 + nj*8 + g]);
            bf[kk][nj][1] = tf32b(W2[(kk*8 + c + 4)*32 + nj*8 + g]);
        }

    // ---- stage V for tile 0 ----
    {
        const float4* src = (const float4*)(g_V + (size_t)bb*Nn*Dn);
        #pragma unroll
        for (int m = 0; m < 8; m++) {
            int f = m*128 + tid;
            int row = f >> 3, q = f & 7;
            *(float4*)&buf[row*36 + q*4] = src[f];
        }
    }
    __syncthreads();

    // ---- precompute fused epilogue matrices (writes done before zw barrier) --
    // M1[c][cc] = sum_d W3[cc][d+1] * Wf1[(32+d)][c]
    #pragma unroll
    for (int pass = 0; pass < 4; pass++) {
        int e = tid + pass*128;        // 0..511
        int cc = e >> 4, cf = e & 15;  // cc 0..31, cf 0..15
        float a = 0.f;
        #pragma unroll
        for (int d = 0; d < 32; d++)
            a += W3s[cc*33 + d + 1] * Wf1[(32+d)*HFn + cf];
        M1[cf*32 + cc] = a;
    }
    if (tid < 16) {
        float a = 0.f;
        #pragma unroll
        for (int d = 0; d < 32; d++) a += b3s[d+1] * Wf1[(32+d)*HFn + tid];
        v1[tid] = a;
    }
    if (tid < 64) {
        const int b = tid >> 4, cf = tid & 15;
        float a = bf1[cf];
        #pragma unroll
        for (int k = 0; k < 32; k++) a += xs[b][k] * Wf1[k*HFn + cf];
        xdot[b][cf] = a;
    }

    float fs = 0.f, fs2 = 0.f;
    const float b3s0 = b3s[0];

    for (int it = 0; it < 4; it++) {
        const int bg = bb + it;

        // ---- fragments + mma ----
        float acc[2][4][4];
        const float* ub = us[it];
        #pragma unroll
        for (int mi = 0; mi < 2; mi++) {
            const int r0 = wrow + mi*16 + g, r1 = r0 + 8;
            int t0 = r0 + (r0 >= i); if (t0 > 127) t0 = 127;
            int t1 = r1 + (r1 >= i); if (t1 > 127) t1 = 127;
            const float sc0 = scs[r0], sh0 = shs[r0];
            const float sc1 = scs[r1], sh1 = shs[r1];

            u32 af[4][4];
            #pragma unroll
            for (int kk = 0; kk < 4; kk++) {
                const int k0 = kk*8 + c, k1 = k0 + 4;
                af[kk][0] = tf32b(leaky((ub[k0] + buf[t0*36 + k0]) * sc0 + sh0));
                af[kk][1] = tf32b(leaky((ub[k0] + buf[t1*36 + k0]) * sc1 + sh1));
                af[kk][2] = tf32b(leaky((ub[k1] + buf[t0*36 + k1]) * sc0 + sh0));
                af[kk][3] = tf32b(leaky((ub[k1] + buf[t1*36 + k1]) * sc1 + sh1));
            }
            #pragma unroll
            for (int nj = 0; nj < 4; nj++) {
                acc[mi][nj][0] = 0.f; acc[mi][nj][1] = 0.f;
                acc[mi][nj][2] = 0.f; acc[mi][nj][3] = 0.f;
                #pragma unroll
                for (int kk = 0; kk < 4; kk++)
                    mma_tf32(acc[mi][nj], af[kk], bf[kk][nj]);
            }
        }

        // ---- epilogue: bias + leaky + gate; z in registers ----
        float zp[8];
        #pragma unroll
        for (int j = 0; j < 8; j++) zp[j] = 0.f;
        float gsum = 0.f;

        #pragma unroll
        for (int mi = 0; mi < 2; mi++) {
            const int r0 = wrow + mi*16 + g, r1 = r0 + 8;
            float d0 = 0.f, d1 = 0.f;
            #pragma unroll
            for (int nj = 0; nj < 4; nj++) {
                const int col0 = nj*8 + c*2;
                acc[mi][nj][0] = leaky(acc[mi][nj][0] + b2s[col0]);
                acc[mi][nj][1] = leaky(acc[mi][nj][1] + b2s[col0+1]);
                acc[mi][nj][2] = leaky(acc[mi][nj][2] + b2s[col0]);
                acc[mi][nj][3] = leaky(acc[mi][nj][3] + b2s[col0+1]);
                d0 += acc[mi][nj][0]*w3c0[col0] + acc[mi][nj][1]*w3c0[col0+1];
                d1 += acc[mi][nj][2]*w3c0[col0] + acc[mi][nj][3]*w3c0[col0+1];
            }
            d0 += __shfl_xor_sync(0xffffffffu, d0, 1);
            d0 += __shfl_xor_sync(0xffffffffu, d0, 2);
            d1 += __shfl_xor_sync(0xffffffffu, d1, 1);
            d1 += __shfl_xor_sync(0xffffffffu, d1, 2);
            float g0  = (r0 < Gn) ? 1.0f/(1.0f + __expf(-(b3s0 + d0))) : 0.f;
            float g1v = (r1 < Gn) ? 1.0f/(1.0f + __expf(-(b3s0 + d1))) : 0.f;
            if (c == 0) {
                if (r0 < Gn) outEdges[(size_t)bg*Pn + i*Gn + r0] = g0;
                if (r1 < Gn) outEdges[(size_t)bg*Pn + i*Gn + r1] = g1v;
            }
            gsum += g0 + g1v;
            #pragma unroll
            for (int nj = 0; nj < 4; nj++) {
                zp[nj*2+0] += g0*acc[mi][nj][0] + g1v*acc[mi][nj][2];
                zp[nj*2+1] += g0*acc[mi][nj][1] + g1v*acc[mi][nj][3];
            }
        }

        #pragma unroll
        for (int s = 4; s <= 16; s <<= 1) {
            #pragma unroll
            for (int j = 0; j < 8; j++)
                zp[j] += __shfl_xor_sync(0xffffffffu, zp[j], s);
            gsum += __shfl_xor_sync(0xffffffffu, gsum, s);
        }
        if (lane < 4) {
            #pragma unroll
            for (int nj = 0; nj < 4; nj++) {
                zw[warp][nj*8 + lane*2 + 0] = zp[nj*2+0];
                zw[warp][nj*8 + lane*2 + 1] = zp[nj*2+1];
            }
        }
        if (lane == 0) zw[warp][32] = gsum;
        __syncthreads();

        // ---- f phase (tid<16, fused agg) overlapped with next-V staging ----
        if (tid < HFn) {
            const float G = zw[0][32] + zw[1][32] + zw[2][32] + zw[3][32];
            float a = xdot[it][tid] + G * v1[tid];
            const float* m1 = &M1[tid*32];
            #pragma unroll
            for (int cc = 0; cc < 32; cc++) {
                float z = zw[0][cc] + zw[1][cc] + zw[2][cc] + zw[3][cc];
                a += z * m1[cc];
            }
            g_f[((size_t)bg*Nn + i)*HFn + tid] = a;
            fs += a; fs2 += a*a;
        } else if (it < 3) {
            const float4* src = (const float4*)(g_V + (size_t)(bg+1)*Nn*Dn);
            #pragma unroll
            for (int m = 0; m < 10; m++) {
                int f = m*112 + (tid - 16);
                if (f < 1024) {
                    int row = f >> 3, q = f & 7;
                    *(float4*)&buf[row*36 + q*4] = src[f];
                }
            }
        }
        __syncthreads();
    }

    if (tid < HFn) {
        atomicAdd(&g_fsum[tid],  fs);
        atomicAdd(&g_fsum2[tid], fs2);
    }
}

// ---------------- Kernel F: final LN (inline params) + MLP -> out -------------
__global__ void kF(const float* __restrict__ gf, const float* __restrict__ bef,
                   const float* __restrict__ Wf2, const float* __restrict__ bf2,
                   float* __restrict__ outp) {
    __shared__ __align__(16) float Wf2s[16*32];
    __shared__ float lnsc[16], lnsh[16], bf2s[32];
    const int tid = threadIdx.x;
    for (int idx = tid; idx < 16*32; idx += 128) Wf2s[idx] = Wf2[idx];
    if (tid < 16) {
        const float invR = 1.0f / 8192.0f;
        float mean = g_fsum[tid] * invR;
        float var  = g_fsum2[tid] * invR - mean * mean;
        float sc = rsqrtf(var + EPSf) * gf[tid];
        lnsc[tid] = sc;
        lnsh[tid] = bef[tid] - mean * sc;
    }
    if (tid < 32) bf2s[tid] = bf2[tid];
    __syncthreads();

    const int gt = blockIdx.x * 128 + tid;
    const int r = gt >> 1;
    const int half = (gt & 1) * 16;

    float gq[16];
    #pragma unroll
    for (int j = 0; j < 16; j++) {
        float v = g_f[(size_t)r*HFn + j];
        gq[j] = leaky(v * lnsc[j] + lnsh[j]);
    }
    float4* op = (float4*)(outp + (size_t)r * Dn + half);
    #pragma unroll
    for (int q = 0; q < 4; q++) {
        float o[4];
        #pragma unroll
        for (int u = 0; u < 4; u++) {
            int cc = half + 4*q + u;
            float a = bf2s[cc];
            #pragma unroll
            for (int j = 0; j < 16; j++) a += gq[j] * Wf2s[j*32 + cc];
            o[u] = a;
        }
        op[q] = make_float4(o[0], o[1], o[2], o[3]);
    }
}

// ---------------- launch ------------------------------------------------------
extern "C" void kernel_launch(void* const* d_in, const int* in_sizes, int n_in,
                              void* d_out, int out_size) {
    const float* inp = (const float*)d_in[0];
    const float* W1  = (const float*)d_in[3];
    const float* b1  = (const float*)d_in[4];
    const float* g1  = (const float*)d_in[5];
    const float* be1 = (const float*)d_in[6];
    const float* W2  = (const float*)d_in[7];
    const float* b2  = (const float*)d_in[8];
    const float* W3  = (const float*)d_in[9];
    const float* b3  = (const float*)d_in[10];
    const float* Wf1 = (const float*)d_in[11];
    const float* bf1 = (const float*)d_in[12];
    const float* gf  = (const float*)d_in[13];
    const float* bef = (const float*)d_in[14];
    const float* Wf2 = (const float*)d_in[15];
    const float* bf2 = (const float*)d_in[16];

    float* outEdges = (float*)d_out;
    float* outFeat  = (float*)d_out + (size_t)Bn * Pn;

    kA<<<Nn, 256>>>(inp, W1, b1);
    kB<<<dim3(8, 8, 8), 256>>>();
    kC<<<dim3(Nn, Bn/4), 128>>>(inp, W2, b2, W3, b3, Wf1, bf1, g1, be1, outEdges);
    kF<<<128, 128>>>(gf, bef, Wf2, bf2, outFeat);
}

// round 15
// speedup vs baseline: 1.0639x; 1.0639x over previous
#include <cuda_runtime.h>
#include <math.h>

#define Bn 64
#define Nn 128
#define Dn 32
#define Gn 127              // N-1
#define Pn (Nn*(Nn-1))      // 16256
#define HFn 16
#define EPSf 1e-5f

typedef unsigned int u32;

// ---------------- scratch (static device globals; no allocation) -------------
__device__ float g_U[Bn*Nn*Dn];
__device__ float g_V[Bn*Nn*Dn];
__device__ float g_sumU[Nn], g_sumU2[Nn], g_sumV[Nn], g_sumV2[Nn];
__device__ float g_C[Nn*Nn];
__device__ float g_f[Bn*Nn*HFn];
__device__ float g_fsum[HFn], g_fsum2[HFn];

__device__ __forceinline__ float leaky(float x) { return x > 0.f ? x : 0.01f * x; }

__device__ __forceinline__ u32 tf32b(float x) {
    u32 y; asm("cvt.rna.tf32.f32 %0, %1;" : "=r"(y) : "f"(x));
    return y;
}
__device__ __forceinline__ void mma_tf32(float* d, const u32* a, const u32* b) {
    asm volatile(
        "mma.sync.aligned.m16n8k8.row.col.f32.tf32.tf32.f32 "
        "{%0,%1,%2,%3}, {%4,%5,%6,%7}, {%8,%9}, {%0,%1,%2,%3};"
        : "+f"(d[0]), "+f"(d[1]), "+f"(d[2]), "+f"(d[3])
        : "r"(a[0]), "r"(a[1]), "r"(a[2]), "r"(a[3]), "r"(b[0]), "r"(b[1]));
}
__device__ __forceinline__ u32 smem_u32(const void* p) {
    u32 a;
    asm("{ .reg .u64 t; cvta.to.shared.u64 t, %1; cvt.u32.u64 %0, t; }" : "=r"(a) : "l"(p));
    return a;
}
__device__ __forceinline__ void cp16(u32 dst, const void* src) {
    asm volatile("cp.async.ca.shared.global [%0], [%1], 16;" :: "r"(dst), "l"(src) : "memory");
}
#define CP_COMMIT() asm volatile("cp.async.commit_group;" ::: "memory")
#define CP_WAIT0()  asm volatile("cp.async.wait_group 0;" ::: "memory")

// ---------------- Kernel A: per-node projections + stats + zeroing -----------
// grid = 128, block = 256: thread = (b 0..63, cq 0..3), 8 channels each
__global__ void kA(const float* __restrict__ inp, const float* __restrict__ W1,
                   const float* __restrict__ b1) {
    const int n = blockIdx.x;
    const int tid = threadIdx.x;
    const int b = tid >> 2, cq = tid & 3;
    __shared__ __align__(16) float W1t[32*64];   // W1t[c*64 + k] = W1[k*32 + c]
    __shared__ float red[64*4];

    if (tid < 128) g_C[n*128 + tid] = 0.f;
    if (n == 0 && tid < HFn) { g_fsum[tid] = 0.f; g_fsum2[tid] = 0.f; }

    for (int idx = tid; idx < 2048; idx += 256) {
        int k = idx & 63, c = idx >> 6;
        W1t[c*64 + k] = W1[k*32 + c];
    }
    __syncthreads();

    float x[32];
    const float4* xp = (const float4*)(inp + ((size_t)b*Nn + n)*Dn);
    #pragma unroll
    for (int q = 0; q < 8; q++) {
        float4 v = xp[q];
        x[4*q+0]=v.x; x[4*q+1]=v.y; x[4*q+2]=v.z; x[4*q+3]=v.w;
    }
    float su=0.f, su2=0.f, sv=0.f, sv2=0.f;
    float ub[8], vb[8];
    #pragma unroll
    for (int cc = 0; cc < 8; cc++) {
        const int c = cq*8 + cc;
        const float4* wr = (const float4*)(W1t + c*64);
        float u = b1[c], v = 0.f;
        #pragma unroll
        for (int j = 0; j < 8; j++) {
            float4 wu = wr[j], wv = wr[8 + j];
            u += x[4*j+0]*wu.x + x[4*j+1]*wu.y + x[4*j+2]*wu.z + x[4*j+3]*wu.w;
            v += x[4*j+0]*wv.x + x[4*j+1]*wv.y + x[4*j+2]*wv.z + x[4*j+3]*wv.w;
        }
        ub[cc] = u; vb[cc] = v;
        su += u; su2 += u*u; sv += v; sv2 += v*v;
    }
    {
        float4* Uo = (float4*)(g_U + ((size_t)b*Nn + n)*Dn + cq*8);
        float4* Vo = (float4*)(g_V + ((size_t)b*Nn + n)*Dn + cq*8);
        Uo[0] = make_float4(ub[0], ub[1], ub[2], ub[3]);
        Uo[1] = make_float4(ub[4], ub[5], ub[6], ub[7]);
        Vo[0] = make_float4(vb[0], vb[1], vb[2], vb[3]);
        Vo[1] = make_float4(vb[4], vb[5], vb[6], vb[7]);
    }
    #pragma unroll
    for (int s = 1; s <= 2; s <<= 1) {
        su  += __shfl_xor_sync(0xffffffffu, su,  s);
        su2 += __shfl_xor_sync(0xffffffffu, su2, s);
        sv  += __shfl_xor_sync(0xffffffffu, sv,  s);
        sv2 += __shfl_xor_sync(0xffffffffu, sv2, s);
    }
    if (cq == 0) { red[b] = su; red[64+b] = su2; red[128+b] = sv; red[192+b] = sv2; }
    __syncthreads();
    for (int s = 32; s > 0; s >>= 1) {
        if (tid < s) {
            red[tid] += red[tid+s]; red[64+tid] += red[64+tid+s];
            red[128+tid] += red[128+tid+s]; red[192+tid] += red[192+tid+s];
        }
        __syncthreads();
    }
    if (tid == 0) {
        g_sumU[n] = red[0]; g_sumU2[n] = red[64];
        g_sumV[n] = red[128]; g_sumV2[n] = red[192];
    }
}

// ---------------- Kernel B: cross term C[s,t], K-split x8 --------------------
__global__ void kB() {
    const int t0 = blockIdx.x * 16;
    const int s0 = blockIdx.y * 16;
    const int bz = blockIdx.z * 8;
    const int tx = threadIdx.x & 15;
    const int ty = threadIdx.x >> 4;
    __shared__ __align__(16) float Us[16][36];
    __shared__ __align__(16) float Vs[16][36];
    float acc = 0.f;
    for (int b = bz; b < bz + 8; b++) {
        __syncthreads();
        {
            int idx = threadIdx.x;
            int r = idx >> 5, c = idx & 31;
            Us[r][c] = g_U[((size_t)b*Nn + s0 + r)*Dn + c];
            Vs[r][c] = g_V[((size_t)b*Nn + t0 + r)*Dn + c];
            idx += 256; r = idx >> 5; c = idx & 31;
            Us[r][c] = g_U[((size_t)b*Nn + s0 + r)*Dn + c];
            Vs[r][c] = g_V[((size_t)b*Nn + t0 + r)*Dn + c];
        }
        __syncthreads();
        #pragma unroll
        for (int q = 0; q < 8; q++) {
            float4 u = *(const float4*)&Us[ty][4*q];
            float4 v = *(const float4*)&Vs[tx][4*q];
            acc += u.x*v.x + u.y*v.y + u.z*v.z + u.w*v.w;
        }
    }
    atomicAdd(&g_C[(s0+ty)*Nn + (t0+tx)], acc);
}

// ---------------- Kernel C: mma.sync tf32, cp.async double-buffered V --------
// grid = (128, 8), block = 128 (4 warps); each CTA does 8 batch tiles.
__global__ void __launch_bounds__(128, 4) kC(
        const float* __restrict__ inp,
        const float* __restrict__ W2, const float* __restrict__ b2,
        const float* __restrict__ W3, const float* __restrict__ b3,
        const float* __restrict__ Wf1, const float* __restrict__ bf1,
        const float* __restrict__ g1, const float* __restrict__ be1,
        float* __restrict__ outEdges) {
    __shared__ __align__(16) float buf[2][128*36];   // double-buffered V
    __shared__ float W3s[1056], w3c0[32], b2s[32], b3s[36];
    __shared__ float us[8][32], xs[8][32], scs[128], shs[128];
    __shared__ float zw[4][36];
    __shared__ float aggs[32];

    const int i   = blockIdx.x;
    const int bb  = blockIdx.y * 8;
    const int tid = threadIdx.x;
    const int warp = tid >> 5;
    const int lane = tid & 31;
    const int g = lane >> 2, c = lane & 3;
    const int wrow = warp * 32;
    const u32 bufb = smem_u32(buf);

    // ---- stage V tile 0 (cp.async) ----
    {
        const char* src = (const char*)(g_V + (size_t)bb*Nn*Dn);
        #pragma unroll
        for (int m = 0; m < 8; m++) {
            int f = m*128 + tid;
            int row = f >> 3, q = f & 7;
            cp16(bufb + row*144 + q*16, src + f*16);
        }
        CP_COMMIT();
    }

    // ---- one-time staging ----
    for (int idx = tid; idx < 1056; idx += 128) W3s[idx] = W3[idx];
    if (tid < 32) { w3c0[tid] = W3[tid*33]; b2s[tid] = b2[tid]; }
    if (tid < 33) b3s[tid] = b3[tid];
    #pragma unroll
    for (int pass = 0; pass < 2; pass++) {
        int idx = tid + pass*128;
        const int b = idx >> 5, k = idx & 31;
        us[b][k] = g_U[((size_t)(bb+b)*Nn + i)*Dn + k];
        xs[b][k] = inp[((size_t)(bb+b)*Nn + i)*Dn + k];
    }
    if (tid < 127) {
        const int t = tid + (tid >= i);
        const int p = i * Gn + tid;
        const float inv = 1.0f / 2048.0f;
        float m  = (g_sumU[i] + g_sumV[t]) * inv;
        float e2 = (g_sumU2[i] + g_sumV2[t] + 2.0f * g_C[i*Nn + t]) * inv;
        float sc = rsqrtf(e2 - m*m + EPSf) * g1[p];
        scs[tid] = sc; shs[tid] = be1[p] - m * sc;
    } else if (tid == 127) { scs[127] = 0.f; shs[127] = 0.f; }

    // ---- B fragments (W2, k x n), tf32, persistent ----
    u32 bf[4][4][2];
    #pragma unroll
    for (int kk = 0; kk < 4; kk++)
        #pragma unroll
        for (int nj = 0; nj < 4; nj++) {
            bf[kk][nj][0] = tf32b(W2[(kk*8 + c)*32 + nj*8 + g]);
            bf[kk][nj][1] = tf32b(W2[(kk*8 + c + 4)*32 + nj*8 + g]);
        }

    CP_WAIT0();
    __syncthreads();

    float fs = 0.f, fs2 = 0.f;
    const float b3s0 = b3s[0];

    for (int it = 0; it < 8; it++) {
        const int bg = bb + it;
        const int cur = it & 1, nxt = cur ^ 1;
        const float* bc = buf[cur];

        // ---- issue cp.async for next tile ----
        if (it < 7) {
            const char* src = (const char*)(g_V + (size_t)(bg+1)*Nn*Dn);
            const u32 dstb = bufb + nxt*18432;
            #pragma unroll
            for (int m = 0; m < 8; m++) {
                int f = m*128 + tid;
                int row = f >> 3, q = f & 7;
                cp16(dstb + row*144 + q*16, src + f*16);
            }
            CP_COMMIT();
        }

        // ---- fragments + mma ----
        float acc[2][4][4];
        const float* ub = us[it];
        #pragma unroll
        for (int mi = 0; mi < 2; mi++) {
            const int r0 = wrow + mi*16 + g, r1 = r0 + 8;
            int t0 = r0 + (r0 >= i); if (t0 > 127) t0 = 127;
            int t1 = r1 + (r1 >= i); if (t1 > 127) t1 = 127;
            const float sc0 = scs[r0], sh0 = shs[r0];
            const float sc1 = scs[r1], sh1 = shs[r1];

            u32 af[4][4];
            #pragma unroll
            for (int kk = 0; kk < 4; kk++) {
                const int k0 = kk*8 + c, k1 = k0 + 4;
                af[kk][0] = tf32b(leaky((ub[k0] + bc[t0*36 + k0]) * sc0 + sh0));
                af[kk][1] = tf32b(leaky((ub[k0] + bc[t1*36 + k0]) * sc1 + sh1));
                af[kk][2] = tf32b(leaky((ub[k1] + bc[t0*36 + k1]) * sc0 + sh0));
                af[kk][3] = tf32b(leaky((ub[k1] + bc[t1*36 + k1]) * sc1 + sh1));
            }
            #pragma unroll
            for (int nj = 0; nj < 4; nj++) {
                acc[mi][nj][0] = 0.f; acc[mi][nj][1] = 0.f;
                acc[mi][nj][2] = 0.f; acc[mi][nj][3] = 0.f;
                #pragma unroll
                for (int kk = 0; kk < 4; kk++)
                    mma_tf32(acc[mi][nj], af[kk], bf[kk][nj]);
            }
        }

        // ---- epilogue: bias + leaky + gate; z in registers ----
        float zp[8];
        #pragma unroll
        for (int j = 0; j < 8; j++) zp[j] = 0.f;
        float gsum = 0.f;

        #pragma unroll
        for (int mi = 0; mi < 2; mi++) {
            const int r0 = wrow + mi*16 + g, r1 = r0 + 8;
            float d0 = 0.f, d1 = 0.f;
            #pragma unroll
            for (int nj = 0; nj < 4; nj++) {
                const int col0 = nj*8 + c*2;
                acc[mi][nj][0] = leaky(acc[mi][nj][0] + b2s[col0]);
                acc[mi][nj][1] = leaky(acc[mi][nj][1] + b2s[col0+1]);
                acc[mi][nj][2] = leaky(acc[mi][nj][2] + b2s[col0]);
                acc[mi][nj][3] = leaky(acc[mi][nj][3] + b2s[col0+1]);
                d0 += acc[mi][nj][0]*w3c0[col0] + acc[mi][nj][1]*w3c0[col0+1];
                d1 += acc[mi][nj][2]*w3c0[col0] + acc[mi][nj][3]*w3c0[col0+1];
            }
            d0 += __shfl_xor_sync(0xffffffffu, d0, 1);
            d0 += __shfl_xor_sync(0xffffffffu, d0, 2);
            d1 += __shfl_xor_sync(0xffffffffu, d1, 1);
            d1 += __shfl_xor_sync(0xffffffffu, d1, 2);
            float g0  = (r0 < Gn) ? 1.0f/(1.0f + __expf(-(b3s0 + d0))) : 0.f;
            float g1v = (r1 < Gn) ? 1.0f/(1.0f + __expf(-(b3s0 + d1))) : 0.f;
            if (c == 0) {
                if (r0 < Gn) outEdges[(size_t)bg*Pn + i*Gn + r0] = g0;
                if (r1 < Gn) outEdges[(size_t)bg*Pn + i*Gn + r1] = g1v;
            }
            gsum += g0 + g1v;
            #pragma unroll
            for (int nj = 0; nj < 4; nj++) {
                zp[nj*2+0] += g0*acc[mi][nj][0] + g1v*acc[mi][nj][2];
                zp[nj*2+1] += g0*acc[mi][nj][1] + g1v*acc[mi][nj][3];
            }
        }

        #pragma unroll
        for (int s = 4; s <= 16; s <<= 1) {
            #pragma unroll
            for (int j = 0; j < 8; j++)
                zp[j] += __shfl_xor_sync(0xffffffffu, zp[j], s);
            gsum += __shfl_xor_sync(0xffffffffu, gsum, s);
        }
        if (lane < 4) {
            #pragma unroll
            for (int nj = 0; nj < 4; nj++) {
                zw[warp][nj*8 + lane*2 + 0] = zp[nj*2+0];
                zw[warp][nj*8 + lane*2 + 1] = zp[nj*2+1];
            }
        }
        if (lane == 0) zw[warp][32] = gsum;
        __syncthreads();

        // ---- warp 0: agg (lanes 0-31) then f (lanes 0-15) ----
        if (warp == 0) {
            const float G = zw[0][32] + zw[1][32] + zw[2][32] + zw[3][32];
            {
                float a = G * b3s[lane + 1];
                #pragma unroll
                for (int cc = 0; cc < 32; cc++) {
                    float z = zw[0][cc] + zw[1][cc] + zw[2][cc] + zw[3][cc];
                    a += z * W3s[cc*33 + (lane + 1)];
                }
                aggs[lane] = a;
            }
            __syncwarp();
            if (lane < HFn) {
                const float* xb = xs[it];
                float a = bf1[lane];
                #pragma unroll
                for (int k = 0; k < 32; k++) a += xb[k] * Wf1[k*HFn + lane];
                #pragma unroll
                for (int k = 0; k < 32; k++) a += aggs[k] * Wf1[(32+k)*HFn + lane];
                g_f[((size_t)bg*Nn + i)*HFn + lane] = a;
                fs += a; fs2 += a*a;
            }
        }
        CP_WAIT0();
        __syncthreads();
    }

    if (tid < HFn) {
        atomicAdd(&g_fsum[tid],  fs);
        atomicAdd(&g_fsum2[tid], fs2);
    }
}

// ---------------- Kernel F: final LN (inline params) + MLP -> out -------------
__global__ void kF(const float* __restrict__ gf, const float* __restrict__ bef,
                   const float* __restrict__ Wf2, const float* __restrict__ bf2,
                   float* __restrict__ outp) {
    __shared__ __align__(16) float Wf2s[16*32];
    __shared__ float lnsc[16], lnsh[16], bf2s[32];
    const int tid = threadIdx.x;
    for (int idx = tid; idx < 16*32; idx += 128) Wf2s[idx] = Wf2[idx];
    if (tid < 16) {
        const float invR = 1.0f / 8192.0f;
        float mean = g_fsum[tid] * invR;
        float var  = g_fsum2[tid] * invR - mean * mean;
        float sc = rsqrtf(var + EPSf) * gf[tid];
        lnsc[tid] = sc;
        lnsh[tid] = bef[tid] - mean * sc;
    }
    if (tid < 32) bf2s[tid] = bf2[tid];
    __syncthreads();

    const int gt = blockIdx.x * 128 + tid;
    const int r = gt >> 1;
    const int half = (gt & 1) * 16;

    float gq[16];
    {
        const float4* fp = (const float4*)(g_f + (size_t)r*HFn);
        #pragma unroll
        for (int q = 0; q < 4; q++) {
            float4 v = fp[q];
            gq[4*q+0] = leaky(v.x * lnsc[4*q+0] + lnsh[4*q+0]);
            gq[4*q+1] = leaky(v.y * lnsc[4*q+1] + lnsh[4*q+1]);
            gq[4*q+2] = leaky(v.z * lnsc[4*q+2] + lnsh[4*q+2]);
            gq[4*q+3] = leaky(v.w * lnsc[4*q+3] + lnsh[4*q+3]);
        }
    }
    float4* op = (float4*)(outp + (size_t)r * Dn + half);
    #pragma unroll
    for (int q = 0; q < 4; q++) {
        float o[4];
        #pragma unroll
        for (int u = 0; u < 4; u++) {
            int cc = half + 4*q + u;
            float a = bf2s[cc];
            #pragma unroll
            for (int j = 0; j < 16; j++) a += gq[j] * Wf2s[j*32 + cc];
            o[u] = a;
        }
        op[q] = make_float4(o[0], o[1], o[2], o[3]);
    }
}

// ---------------- launch ------------------------------------------------------
extern "C" void kernel_launch(void* const* d_in, const int* in_sizes, int n_in,
                              void* d_out, int out_size) {
    const float* inp = (const float*)d_in[0];
    const float* W1  = (const float*)d_in[3];
    const float* b1  = (const float*)d_in[4];
    const float* g1  = (const float*)d_in[5];
    const float* be1 = (const float*)d_in[6];
    const float* W2  = (const float*)d_in[7];
    const float* b2  = (const float*)d_in[8];
    const float* W3  = (const float*)d_in[9];
    const float* b3  = (const float*)d_in[10];
    const float* Wf1 = (const float*)d_in[11];
    const float* bf1 = (const float*)d_in[12];
    const float* gf  = (const float*)d_in[13];
    const float* bef = (const float*)d_in[14];
    const float* Wf2 = (const float*)d_in[15];
    const float* bf2 = (const float*)d_in[16];

    float* outEdges = (float*)d_out;
    float* outFeat  = (float*)d_out + (size_t)Bn * Pn;

    kA<<<Nn, 256>>>(inp, W1, b1);
    kB<<<dim3(8, 8, 8), 256>>>();
    kC<<<dim3(Nn, Bn/8), 128>>>(inp, W2, b2, W3, b3, Wf1, bf1, g1, be1, outEdges);
    kF<<<128, 128>>>(gf, bef, Wf2, bf2, outFeat);
}

// round 16
// speedup vs baseline: 1.0928x; 1.0272x over previous
#include <cuda_runtime.h>
#include <math.h>

#define Bn 64
#define Nn 128
#define Dn 32
#define Gn 127              // N-1
#define Pn (Nn*(Nn-1))      // 16256
#define HFn 16
#define EPSf 1e-5f

typedef unsigned int u32;

// ---------------- scratch (static device globals; no allocation) -------------
__device__ float g_U[Bn*Nn*Dn];
__device__ float g_V[Bn*Nn*Dn];
__device__ float g_sumU[Nn], g_sumU2[Nn], g_sumV[Nn], g_sumV2[Nn];
__device__ float g_C[Nn*Nn];
__device__ float g_f[Bn*Nn*HFn];
__device__ float g_fsum[HFn], g_fsum2[HFn];

__device__ __forceinline__ float leaky(float x) { return x > 0.f ? x : 0.01f * x; }

__device__ __forceinline__ u32 tf32b(float x) {
    u32 y; asm("cvt.rna.tf32.f32 %0, %1;" : "=r"(y) : "f"(x));
    return y;
}
__device__ __forceinline__ void mma_tf32(float* d, const u32* a, const u32* b) {
    asm volatile(
        "mma.sync.aligned.m16n8k8.row.col.f32.tf32.tf32.f32 "
        "{%0,%1,%2,%3}, {%4,%5,%6,%7}, {%8,%9}, {%0,%1,%2,%3};"
        : "+f"(d[0]), "+f"(d[1]), "+f"(d[2]), "+f"(d[3])
        : "r"(a[0]), "r"(a[1]), "r"(a[2]), "r"(a[3]), "r"(b[0]), "r"(b[1]));
}
__device__ __forceinline__ u32 smem_u32(const void* p) {
    u32 a;
    asm("{ .reg .u64 t; cvta.to.shared.u64 t, %1; cvt.u32.u64 %0, t; }" : "=r"(a) : "l"(p));
    return a;
}
__device__ __forceinline__ void cp16(u32 dst, const void* src) {
    asm volatile("cp.async.ca.shared.global [%0], [%1], 16;" :: "r"(dst), "l"(src) : "memory");
}
#define CP_COMMIT() asm volatile("cp.async.commit_group;" ::: "memory")
#define CP_WAIT0()  asm volatile("cp.async.wait_group 0;" ::: "memory")

// ---------------- Kernel A: per-node projections + stats + zeroing -----------
__global__ void kA(const float* __restrict__ inp, const float* __restrict__ W1,
                   const float* __restrict__ b1) {
    const int n = blockIdx.x;
    const int tid = threadIdx.x;
    const int b = tid >> 2, cq = tid & 3;
    __shared__ __align__(16) float W1t[32*64];
    __shared__ float red[64*4];

    if (tid < 128) g_C[n*128 + tid] = 0.f;
    if (n == 0 && tid < HFn) { g_fsum[tid] = 0.f; g_fsum2[tid] = 0.f; }

    for (int idx = tid; idx < 2048; idx += 256) {
        int k = idx & 63, c = idx >> 6;
        W1t[c*64 + k] = W1[k*32 + c];
    }
    __syncthreads();

    float x[32];
    const float4* xp = (const float4*)(inp + ((size_t)b*Nn + n)*Dn);
    #pragma unroll
    for (int q = 0; q < 8; q++) {
        float4 v = xp[q];
        x[4*q+0]=v.x; x[4*q+1]=v.y; x[4*q+2]=v.z; x[4*q+3]=v.w;
    }
    float su=0.f, su2=0.f, sv=0.f, sv2=0.f;
    float ub[8], vb[8];
    #pragma unroll
    for (int cc = 0; cc < 8; cc++) {
        const int c = cq*8 + cc;
        const float4* wr = (const float4*)(W1t + c*64);
        float u = b1[c], v = 0.f;
        #pragma unroll
        for (int j = 0; j < 8; j++) {
            float4 wu = wr[j], wv = wr[8 + j];
            u += x[4*j+0]*wu.x + x[4*j+1]*wu.y + x[4*j+2]*wu.z + x[4*j+3]*wu.w;
            v += x[4*j+0]*wv.x + x[4*j+1]*wv.y + x[4*j+2]*wv.z + x[4*j+3]*wv.w;
        }
        ub[cc] = u; vb[cc] = v;
        su += u; su2 += u*u; sv += v; sv2 += v*v;
    }
    {
        float4* Uo = (float4*)(g_U + ((size_t)b*Nn + n)*Dn + cq*8);
        float4* Vo = (float4*)(g_V + ((size_t)b*Nn + n)*Dn + cq*8);
        Uo[0] = make_float4(ub[0], ub[1], ub[2], ub[3]);
        Uo[1] = make_float4(ub[4], ub[5], ub[6], ub[7]);
        Vo[0] = make_float4(vb[0], vb[1], vb[2], vb[3]);
        Vo[1] = make_float4(vb[4], vb[5], vb[6], vb[7]);
    }
    #pragma unroll
    for (int s = 1; s <= 2; s <<= 1) {
        su  += __shfl_xor_sync(0xffffffffu, su,  s);
        su2 += __shfl_xor_sync(0xffffffffu, su2, s);
        sv  += __shfl_xor_sync(0xffffffffu, sv,  s);
        sv2 += __shfl_xor_sync(0xffffffffu, sv2, s);
    }
    if (cq == 0) { red[b] = su; red[64+b] = su2; red[128+b] = sv; red[192+b] = sv2; }
    __syncthreads();
    for (int s = 32; s > 0; s >>= 1) {
        if (tid < s) {
            red[tid] += red[tid+s]; red[64+tid] += red[64+tid+s];
            red[128+tid] += red[128+tid+s]; red[192+tid] += red[192+tid+s];
        }
        __syncthreads();
    }
    if (tid == 0) {
        g_sumU[n] = red[0]; g_sumU2[n] = red[64];
        g_sumV[n] = red[128]; g_sumV2[n] = red[192];
    }
}

// ---------------- Kernel B: cross term C[s,t], K-split x8 --------------------
__global__ void kB() {
    const int t0 = blockIdx.x * 16;
    const int s0 = blockIdx.y * 16;
    const int bz = blockIdx.z * 8;
    const int tx = threadIdx.x & 15;
    const int ty = threadIdx.x >> 4;
    __shared__ __align__(16) float Us[16][36];
    __shared__ __align__(16) float Vs[16][36];
    float acc = 0.f;
    for (int b = bz; b < bz + 8; b++) {
        __syncthreads();
        {
            int idx = threadIdx.x;
            int r = idx >> 5, c = idx & 31;
            Us[r][c] = g_U[((size_t)b*Nn + s0 + r)*Dn + c];
            Vs[r][c] = g_V[((size_t)b*Nn + t0 + r)*Dn + c];
            idx += 256; r = idx >> 5; c = idx & 31;
            Us[r][c] = g_U[((size_t)b*Nn + s0 + r)*Dn + c];
            Vs[r][c] = g_V[((size_t)b*Nn + t0 + r)*Dn + c];
        }
        __syncthreads();
        #pragma unroll
        for (int q = 0; q < 8; q++) {
            float4 u = *(const float4*)&Us[ty][4*q];
            float4 v = *(const float4*)&Vs[tx][4*q];
            acc += u.x*v.x + u.y*v.y + u.z*v.z + u.w*v.w;
        }
    }
    atomicAdd(&g_C[(s0+ty)*Nn + (t0+tx)], acc);
}

// ---------------- Kernel C: mma.sync tf32, deferred parallel f ---------------
// grid = (128, 8), block = 128 (4 warps); each CTA does 8 batch tiles.
__global__ void __launch_bounds__(128, 4) kC(
        const float* __restrict__ inp,
        const float* __restrict__ W2, const float* __restrict__ b2,
        const float* __restrict__ W3, const float* __restrict__ b3,
        const float* __restrict__ Wf1, const float* __restrict__ bf1,
        const float* __restrict__ g1, const float* __restrict__ be1,
        float* __restrict__ outEdges) {
    __shared__ __align__(16) float buf[2][128*36];   // double-buffered V
    __shared__ float W3s[1056], w3c0[32], b2s[32], b3s[36];
    __shared__ float us[8][32], xs[8][32], scs[128], shs[128];
    __shared__ float z8[8][4][36];                   // per-tile per-warp col sums + G
    __shared__ float M1[16*32], v1[16], xdot[8*16];
    __shared__ float fsum_s[16], fsum2_s[16];

    const int i   = blockIdx.x;
    const int bb  = blockIdx.y * 8;
    const int tid = threadIdx.x;
    const int warp = tid >> 5;
    const int lane = tid & 31;
    const int g = lane >> 2, c = lane & 3;
    const int wrow = warp * 32;
    const u32 bufb = smem_u32(buf);

    // ---- stage V tile 0 (cp.async) ----
    {
        const char* src = (const char*)(g_V + (size_t)bb*Nn*Dn);
        #pragma unroll
        for (int m = 0; m < 8; m++) {
            int f = m*128 + tid;
            int row = f >> 3, q = f & 7;
            cp16(bufb + row*144 + q*16, src + f*16);
        }
        CP_COMMIT();
    }

    // ---- one-time staging ----
    for (int idx = tid; idx < 1056; idx += 128) W3s[idx] = W3[idx];
    if (tid < 32) { w3c0[tid] = W3[tid*33]; b2s[tid] = b2[tid]; }
    if (tid < 33) b3s[tid] = b3[tid];
    if (tid < 16) { fsum_s[tid] = 0.f; fsum2_s[tid] = 0.f; }
    #pragma unroll
    for (int pass = 0; pass < 2; pass++) {
        int idx = tid + pass*128;
        const int b = idx >> 5, k = idx & 31;
        us[b][k] = g_U[((size_t)(bb+b)*Nn + i)*Dn + k];
        xs[b][k] = inp[((size_t)(bb+b)*Nn + i)*Dn + k];
    }
    if (tid < 127) {
        const int t = tid + (tid >= i);
        const int p = i * Gn + tid;
        const float inv = 1.0f / 2048.0f;
        float m  = (g_sumU[i] + g_sumV[t]) * inv;
        float e2 = (g_sumU2[i] + g_sumV2[t] + 2.0f * g_C[i*Nn + t]) * inv;
        float sc = rsqrtf(e2 - m*m + EPSf) * g1[p];
        scs[tid] = sc; shs[tid] = be1[p] - m * sc;
    } else if (tid == 127) { scs[127] = 0.f; shs[127] = 0.f; }

    // ---- B fragments (W2, k x n), tf32, persistent ----
    u32 bf[4][4][2];
    #pragma unroll
    for (int kk = 0; kk < 4; kk++)
        #pragma unroll
        for (int nj = 0; nj < 4; nj++) {
            bf[kk][nj][0] = tf32b(W2[(kk*8 + c)*32 + nj*8 + g]);
            bf[kk][nj][1] = tf32b(W2[(kk*8 + c + 4)*32 + nj*8 + g]);
        }

    CP_WAIT0();
    __syncthreads();

    // ---- fused-epilogue precompute (once per CTA, amortized over 8 tiles) ----
    // M1[cf][cc] = sum_d W3[cc][d+1] * Wf1[(32+d)][cf]
    #pragma unroll
    for (int pass = 0; pass < 4; pass++) {
        int e = tid + pass*128;        // 0..511
        int cc = e >> 4, cf = e & 15;
        float a = 0.f;
        #pragma unroll
        for (int d = 0; d < 32; d++)
            a += W3s[cc*33 + d + 1] * Wf1[(32+d)*HFn + cf];
        M1[cf*32 + cc] = a;
    }
    if (tid < 16) {
        float a = 0.f;
        #pragma unroll
        for (int d = 0; d < 32; d++) a += b3s[d+1] * Wf1[(32+d)*HFn + tid];
        v1[tid] = a;
    }
    {
        const int b = tid >> 4, cf = tid & 15;   // 128 threads = 8 batches x 16
        float a = bf1[cf];
        #pragma unroll
        for (int k = 0; k < 32; k++) a += xs[b][k] * Wf1[k*HFn + cf];
        xdot[tid] = a;
    }

    const float b3s0 = b3s[0];

    for (int it = 0; it < 8; it++) {
        const int bg = bb + it;
        const int cur = it & 1, nxt = cur ^ 1;
        const float* bc = buf[cur];

        // ---- issue cp.async for next tile ----
        if (it < 7) {
            const char* src = (const char*)(g_V + (size_t)(bg+1)*Nn*Dn);
            const u32 dstb = bufb + nxt*18432;
            #pragma unroll
            for (int m = 0; m < 8; m++) {
                int f = m*128 + tid;
                int row = f >> 3, q = f & 7;
                cp16(dstb + row*144 + q*16, src + f*16);
            }
            CP_COMMIT();
        }

        // ---- fragments + mma ----
        float acc[2][4][4];
        const float* ub = us[it];
        #pragma unroll
        for (int mi = 0; mi < 2; mi++) {
            const int r0 = wrow + mi*16 + g, r1 = r0 + 8;
            int t0 = r0 + (r0 >= i); if (t0 > 127) t0 = 127;
            int t1 = r1 + (r1 >= i); if (t1 > 127) t1 = 127;
            const float sc0 = scs[r0], sh0 = shs[r0];
            const float sc1 = scs[r1], sh1 = shs[r1];

            u32 af[4][4];
            #pragma unroll
            for (int kk = 0; kk < 4; kk++) {
                const int k0 = kk*8 + c, k1 = k0 + 4;
                af[kk][0] = tf32b(leaky((ub[k0] + bc[t0*36 + k0]) * sc0 + sh0));
                af[kk][1] = tf32b(leaky((ub[k0] + bc[t1*36 + k0]) * sc1 + sh1));
                af[kk][2] = tf32b(leaky((ub[k1] + bc[t0*36 + k1]) * sc0 + sh0));
                af[kk][3] = tf32b(leaky((ub[k1] + bc[t1*36 + k1]) * sc1 + sh1));
            }
            #pragma unroll
            for (int nj = 0; nj < 4; nj++) {
                acc[mi][nj][0] = 0.f; acc[mi][nj][1] = 0.f;
                acc[mi][nj][2] = 0.f; acc[mi][nj][3] = 0.f;
                #pragma unroll
                for (int kk = 0; kk < 4; kk++)
                    mma_tf32(acc[mi][nj], af[kk], bf[kk][nj]);
            }
        }

        // ---- epilogue: bias + leaky + gate; z in registers ----
        float zp[8];
        #pragma unroll
        for (int j = 0; j < 8; j++) zp[j] = 0.f;
        float gsum = 0.f;

        #pragma unroll
        for (int mi = 0; mi < 2; mi++) {
            const int r0 = wrow + mi*16 + g, r1 = r0 + 8;
            float d0 = 0.f, d1 = 0.f;
            #pragma unroll
            for (int nj = 0; nj < 4; nj++) {
                const int col0 = nj*8 + c*2;
                acc[mi][nj][0] = leaky(acc[mi][nj][0] + b2s[col0]);
                acc[mi][nj][1] = leaky(acc[mi][nj][1] + b2s[col0+1]);
                acc[mi][nj][2] = leaky(acc[mi][nj][2] + b2s[col0]);
                acc[mi][nj][3] = leaky(acc[mi][nj][3] + b2s[col0+1]);
                d0 += acc[mi][nj][0]*w3c0[col0] + acc[mi][nj][1]*w3c0[col0+1];
                d1 += acc[mi][nj][2]*w3c0[col0] + acc[mi][nj][3]*w3c0[col0+1];
            }
            d0 += __shfl_xor_sync(0xffffffffu, d0, 1);
            d0 += __shfl_xor_sync(0xffffffffu, d0, 2);
            d1 += __shfl_xor_sync(0xffffffffu, d1, 1);
            d1 += __shfl_xor_sync(0xffffffffu, d1, 2);
            float g0  = (r0 < Gn) ? 1.0f/(1.0f + __expf(-(b3s0 + d0))) : 0.f;
            float g1v = (r1 < Gn) ? 1.0f/(1.0f + __expf(-(b3s0 + d1))) : 0.f;
            if (c == 0) {
                if (r0 < Gn) outEdges[(size_t)bg*Pn + i*Gn + r0] = g0;
                if (r1 < Gn) outEdges[(size_t)bg*Pn + i*Gn + r1] = g1v;
            }
            gsum += g0 + g1v;
            #pragma unroll
            for (int nj = 0; nj < 4; nj++) {
                zp[nj*2+0] += g0*acc[mi][nj][0] + g1v*acc[mi][nj][2];
                zp[nj*2+1] += g0*acc[mi][nj][1] + g1v*acc[mi][nj][3];
            }
        }

        #pragma unroll
        for (int s = 4; s <= 16; s <<= 1) {
            #pragma unroll
            for (int j = 0; j < 8; j++)
                zp[j] += __shfl_xor_sync(0xffffffffu, zp[j], s);
            gsum += __shfl_xor_sync(0xffffffffu, gsum, s);
        }
        // each warp writes its own z8 slot (no cross-warp hazard, no barrier)
        if (lane < 4) {
            #pragma unroll
            for (int nj = 0; nj < 4; nj++) {
                z8[it][warp][nj*8 + lane*2 + 0] = zp[nj*2+0];
                z8[it][warp][nj*8 + lane*2 + 1] = zp[nj*2+1];
            }
        }
        if (lane == 0) z8[it][warp][32] = gsum;

        CP_WAIT0();
        __syncthreads();   // buffer protection + (final iter) z8 visibility
    }

    // ---- deferred f phase: 128 threads = 8 tiles x 16 channels --------------
    {
        const int itf = tid >> 4, cf = tid & 15;
        const float G = z8[itf][0][32] + z8[itf][1][32]
                      + z8[itf][2][32] + z8[itf][3][32];
        float a = xdot[tid] + G * v1[cf];
        const float* m1 = &M1[cf*32];
        #pragma unroll
        for (int cc = 0; cc < 32; cc++) {
            float z = z8[itf][0][cc] + z8[itf][1][cc]
                    + z8[itf][2][cc] + z8[itf][3][cc];
            a += z * m1[cc];
        }
        g_f[((size_t)(bb+itf)*Nn + i)*HFn + cf] = a;
        atomicAdd(&fsum_s[cf],  a);
        atomicAdd(&fsum2_s[cf], a*a);
    }
    __syncthreads();
    if (tid < HFn) {
        atomicAdd(&g_fsum[tid],  fsum_s[tid]);
        atomicAdd(&g_fsum2[tid], fsum2_s[tid]);
    }
}

// ---------------- Kernel F: final LN (inline params) + MLP -> out -------------
__global__ void kF(const float* __restrict__ gf, const float* __restrict__ bef,
                   const float* __restrict__ Wf2, const float* __restrict__ bf2,
                   float* __restrict__ outp) {
    __shared__ __align__(16) float Wf2s[16*32];
    __shared__ float lnsc[16], lnsh[16], bf2s[32];
    const int tid = threadIdx.x;
    for (int idx = tid; idx < 16*32; idx += 128) Wf2s[idx] = Wf2[idx];
    if (tid < 16) {
        const float invR = 1.0f / 8192.0f;
        float mean = g_fsum[tid] * invR;
        float var  = g_fsum2[tid] * invR - mean * mean;
        float sc = rsqrtf(var + EPSf) * gf[tid];
        lnsc[tid] = sc;
        lnsh[tid] = bef[tid] - mean * sc;
    }
    if (tid < 32) bf2s[tid] = bf2[tid];
    __syncthreads();

    const int gt = blockIdx.x * 128 + tid;
    const int r = gt >> 1;
    const int half = (gt & 1) * 16;

    float gq[16];
    {
        const float4* fp = (const float4*)(g_f + (size_t)r*HFn);
        #pragma unroll
        for (int q = 0; q < 4; q++) {
            float4 v = fp[q];
            gq[4*q+0] = leaky(v.x * lnsc[4*q+0] + lnsh[4*q+0]);
            gq[4*q+1] = leaky(v.y * lnsc[4*q+1] + lnsh[4*q+1]);
            gq[4*q+2] = leaky(v.z * lnsc[4*q+2] + lnsh[4*q+2]);
            gq[4*q+3] = leaky(v.w * lnsc[4*q+3] + lnsh[4*q+3]);
        }
    }
    float4* op = (float4*)(outp + (size_t)r * Dn + half);
    #pragma unroll
    for (int q = 0; q < 4; q++) {
        float o[4];
        #pragma unroll
        for (int u = 0; u < 4; u++) {
            int cc = half + 4*q + u;
            float a = bf2s[cc];
            #pragma unroll
            for (int j = 0; j < 16; j++) a += gq[j] * Wf2s[j*32 + cc];
            o[u] = a;
        }
        op[q] = make_float4(o[0], o[1], o[2], o[3]);
    }
}

// ---------------- launch ------------------------------------------------------
extern "C" void kernel_launch(void* const* d_in, const int* in_sizes, int n_in,
                              void* d_out, int out_size) {
    const float* inp = (const float*)d_in[0];
    const float* W1  = (const float*)d_in[3];
    const float* b1  = (const float*)d_in[4];
    const float* g1  = (const float*)d_in[5];
    const float* be1 = (const float*)d_in[6];
    const float* W2  = (const float*)d_in[7];
    const float* b2  = (const float*)d_in[8];
    const float* W3  = (const float*)d_in[9];
    const float* b3  = (const float*)d_in[10];
    const float* Wf1 = (const float*)d_in[11];
    const float* bf1 = (const float*)d_in[12];
    const float* gf  = (const float*)d_in[13];
    const float* bef = (const float*)d_in[14];
    const float* Wf2 = (const float*)d_in[15];
    const float* bf2 = (const float*)d_in[16];

    float* outEdges = (float*)d_out;
    float* outFeat  = (float*)d_out + (size_t)Bn * Pn;

    kA<<<Nn, 256>>>(inp, W1, b1);
    kB<<<dim3(8, 8, 8), 256>>>();
    kC<<<dim3(Nn, Bn/8), 128>>>(inp, W2, b2, W3, b3, Wf1, bf1, g1, be1, outEdges);
    kF<<<128, 128>>>(gf, bef, Wf2, bf2, outFeat);
}